// round 9
// baseline (speedup 1.0000x reference)
#include <cuda_runtime.h>
#include <cuda_bf16.h>
#include <stdint.h>
#include <math.h>

#define HID 128
#define INP 320
#define CIN 448
#define BATCH 8
#define IMH 64
#define IMW 128
#define NCH 14                    // 448/32 channel chunks

typedef unsigned long long u64;

// ---- smem byte layout ----
#define OFF_B   1024              // 2 x 16384 (B act tiles, SW128, [px][64 bf16])
#define OFF_WD  (OFF_B + 32768)   // 448*9*4 = 16128 (dw weights fp32)
#define OFF_IN  (OFF_WD + 16128)  // 2 x 32 x 216 floats (halo tiles, rows 6x36)
#define IN_STRIDE 216
#define SMEM_BYTES (OFF_IN + 2*32*IN_STRIDE*4)   // 105216
#define EP_STRIDE 132             // epilogue stage stride (floats)

// ---- device scratch ----
__device__ float g_z [BATCH*HID*IMH*IMW];
__device__ float g_rh[BATCH*HID*IMH*IMW];
__device__ float g_wd[3][CIN*9];
// A operands pre-arranged in mma fragment layout:
// byte off = ((((ci*4+mw)*2+ma)*4+ks)*32 + lane)*16 + reg*4 + half*2
__device__ __align__(16) __nv_bfloat16 g_wpAf[3][NCH*4*2*4*32*8];
__device__ float g_wpscale[3];

// ---- helpers ----
__device__ __forceinline__ unsigned swz(unsigned off) { return off ^ ((off >> 3) & 0x70); }
__device__ __forceinline__ float sigmoidf_(float v) { return 1.0f / (1.0f + expf(-v)); }
__device__ __forceinline__ void cpa4(unsigned d, const float* s, bool ok) {
    asm volatile("cp.async.ca.shared.global [%0], [%1], 4, %2;"
                 :: "r"(d), "l"(s), "r"(ok ? 4 : 0) : "memory");
}
__device__ __forceinline__ void cpa16(unsigned d, const void* s) {
    asm volatile("cp.async.cg.shared.global [%0], [%1], 16;" :: "r"(d), "l"(s) : "memory");
}
__device__ __forceinline__ void cp_commit() { asm volatile("cp.async.commit_group;" ::: "memory"); }
__device__ __forceinline__ void cp_wait0()  { asm volatile("cp.async.wait_group 0;" ::: "memory"); }
__device__ __forceinline__ unsigned pack_bf2(float up, float lo) {  // {upper=up, lower=lo}
    unsigned r;
    asm("cvt.rn.bf16x2.f32 %0, %1, %2;" : "=r"(r) : "f"(up), "f"(lo));
    return r;
}
__device__ __forceinline__ void ldm_x4(unsigned addr, unsigned* r) {
    asm volatile("ldmatrix.sync.aligned.m8n8.x4.shared.b16 {%0,%1,%2,%3}, [%4];"
                 : "=r"(r[0]), "=r"(r[1]), "=r"(r[2]), "=r"(r[3]) : "r"(addr));
}
__device__ __forceinline__ void mma16816(float* d, const unsigned* a, unsigned b0, unsigned b1) {
    asm volatile("mma.sync.aligned.m16n8k16.row.col.f32.bf16.bf16.f32 "
                 "{%0,%1,%2,%3}, {%4,%5,%6,%7}, {%8,%9}, {%0,%1,%2,%3};"
                 : "+f"(d[0]), "+f"(d[1]), "+f"(d[2]), "+f"(d[3])
                 : "r"(a[0]), "r"(a[1]), "r"(a[2]), "r"(a[3]), "r"(b0), "r"(b1));
}

// ---- weight fake-quant prep ----
__global__ void quant_prep_kernel(const float* wdz, const float* wpz,
                                  const float* wdr, const float* wpr,
                                  const float* wdq, const float* wpq) {
    const int which = blockIdx.x;
    const float* src = nullptr; int n = 0; float* dst_dw = nullptr;
    __nv_bfloat16* dst_pw = nullptr; const int g = which >> 1;
    switch (which) {
        case 0: src = wdz; n = CIN*9;   dst_dw = g_wd[0];   break;
        case 1: src = wpz; n = CIN*HID; dst_pw = g_wpAf[0]; break;
        case 2: src = wdr; n = CIN*9;   dst_dw = g_wd[1];   break;
        case 3: src = wpr; n = CIN*HID; dst_pw = g_wpAf[1]; break;
        case 4: src = wdq; n = CIN*9;   dst_dw = g_wd[2];   break;
        default:src = wpq; n = CIN*HID; dst_pw = g_wpAf[2]; break;
    }
    __shared__ float red[256];
    __shared__ float s_scale;
    const int tid = threadIdx.x;
    float m = 0.0f;
    for (int i = tid; i < n; i += 256) m = fmaxf(m, fabsf(src[i]));
    red[tid] = m; __syncthreads();
    for (int s = 128; s > 0; s >>= 1) {
        if (tid < s) red[tid] = fmaxf(red[tid], red[tid + s]);
        __syncthreads();
    }
    if (tid == 0) { s_scale = fmaxf(red[0], 1e-8f) / 127.0f; if (dst_pw) g_wpscale[g] = s_scale; }
    __syncthreads();
    const float scale = s_scale;
    for (int i = tid; i < n; i += 256) {
        float q = rintf(src[i] / scale);               // round-half-even == jnp.round
        q = fminf(fmaxf(q, -128.0f), 127.0f);
        if (dst_dw) {
            dst_dw[i] = q * scale;
        } else {
            // scatter q (exact in bf16) into mma A-fragment layout, cols k (hi) and k+32 (lo)
            const int o = i / CIN, c = i - o * CIN;
            const int ci = c >> 5, k = c & 31;
            const __nv_bfloat16 qb = __float2bfloat16(q);
            const int mw = o >> 5, ma = (o >> 4) & 1, r = o & 15;
#pragma unroll
            for (int t = 0; t < 2; t++) {
                const int kk = k + t * 32;
                const int ks = kk >> 4, c16 = kk & 15;
                const int lane = ((r & 7) << 2) | ((c16 & 7) >> 1);
                const int reg = ((r >> 3) & 1) | (((c16 >> 3) & 1) << 1);
                const int idx = (((((ci * 4 + mw) * 2 + ma) * 4 + ks) * 32 + lane) << 3)
                              + (reg << 1) + (c16 & 1);
                dst_pw[idx] = qb;
            }
        }
    }
}

// ---- fused gate kernel ----
// MODE 0: z = sigmoid(pw(dw(hx)))             -> g_z
// MODE 1: rh = sigmoid(pw(dw(hx))) * h        -> g_rh
// MODE 2: out = (1-z)*h + z*tanh(pw(dw(rhx))) -> dout
template <int MODE>
__global__ void __launch_bounds__(256, 1)
gate_kernel(const float* __restrict__ h, const float* __restrict__ x,
            const float* __restrict__ bd, const float* __restrict__ bp,
            float* __restrict__ dout) {
    extern __shared__ __align__(1024) char smem[];
    float* smf = reinterpret_cast<float*>(smem);
    const unsigned su = (unsigned)__cvta_generic_to_shared(smem);

    const int tid = threadIdx.x;
    const int wid = tid >> 5;
    const int lid = tid & 31;
    const int b  = blockIdx.z;
    const int y0 = blockIdx.y << 2;
    const int x0 = blockIdx.x << 5;

    const float* in0 = (MODE == 2) ? g_rh : h;
    const float* s_wd = smf + OFF_WD / 4;

    // staging map
    const int sch = tid >> 3, l8 = tid & 7;
    auto stage_in = [&](int ci, int buf) {
        const int cg = (ci << 5) + sch;
        const float* pl = (cg < HID) ? (in0 + (((size_t)b * HID + cg) << 13))
                                     : (x   + (((size_t)b * INP + (cg - HID)) << 13));
        const unsigned sb = su + OFF_IN + ((buf * 32 + sch) * IN_STRIDE) * 4;
#pragma unroll
        for (int row = 0; row < 6; row++) {
            const int gy = y0 + row - 1;
            const bool rok = (unsigned)gy < (unsigned)IMH;
#pragma unroll
            for (int s = 0; s < 5; s++) {
                const int col = l8 + (s << 3);
                if (col < 34) {
                    const int gx = x0 + col - 1;
                    const bool ok = rok && ((unsigned)gx < (unsigned)IMW);
                    cpa4(sb + (row * 36 + col) * 4, pl + (ok ? ((gy << 7) + gx) : 0), ok);
                }
            }
        }
    };

    // dw map: ch pair cp, pixel group pg (8 px)
    const int cp = tid & 15, pg = tid >> 4;
    const int pr = pg >> 2, pc0 = (pg & 3) << 3;

    // mma map: warp = (mw, nw)
    const int mw = wid & 3, nw = wid >> 2;
    const int bRow = ((lid >> 4) << 3) + (lid & 7);
    const int bChunk = ((lid >> 3) & 1) << 4;

    float acc[2][8][4];
#pragma unroll
    for (int i = 0; i < 2; i++)
#pragma unroll
        for (int j = 0; j < 8; j++)
#pragma unroll
            for (int k = 0; k < 4; k++) acc[i][j][k] = 0.0f;

    // ---- depthwise block: chunk ci into B[buf] ----
    auto dw_block = [&](int ci, int buf) {
        const int k0 = cp << 1, c0 = (ci << 5) + k0;
        float wA[9], wB[9];
#pragma unroll
        for (int t = 0; t < 9; t++) { wA[t] = s_wd[c0 * 9 + t]; wB[t] = s_wd[(c0 + 1) * 9 + t]; }
        float oA[8], oB[8];
        const float bA = __ldg(bd + c0), bB = __ldg(bd + c0 + 1);
#pragma unroll
        for (int j = 0; j < 8; j++) { oA[j] = bA; oB[j] = bB; }
        const float* baseA = smf + OFF_IN / 4 + (buf * 32 + k0) * IN_STRIDE + pr * 36 + pc0;
#pragma unroll
        for (int r = 0; r < 3; r++) {
            float rowA[12], rowB[12];
            *reinterpret_cast<float4*>(rowA)     = *reinterpret_cast<const float4*>(baseA + r * 36);
            *reinterpret_cast<float4*>(rowA + 4) = *reinterpret_cast<const float4*>(baseA + r * 36 + 4);
            *reinterpret_cast<float4*>(rowA + 8) = *reinterpret_cast<const float4*>(baseA + r * 36 + 8);
            const float* baseB = baseA + IN_STRIDE;
            *reinterpret_cast<float4*>(rowB)     = *reinterpret_cast<const float4*>(baseB + r * 36);
            *reinterpret_cast<float4*>(rowB + 4) = *reinterpret_cast<const float4*>(baseB + r * 36 + 4);
            *reinterpret_cast<float4*>(rowB + 8) = *reinterpret_cast<const float4*>(baseB + r * 36 + 8);
#pragma unroll
            for (int j = 0; j < 8; j++) {
                oA[j] = fmaf(wA[r*3+0], rowA[j], oA[j]);
                oA[j] = fmaf(wA[r*3+1], rowA[j+1], oA[j]);
                oA[j] = fmaf(wA[r*3+2], rowA[j+2], oA[j]);
                oB[j] = fmaf(wB[r*3+0], rowB[j], oB[j]);
                oB[j] = fmaf(wB[r*3+1], rowB[j+1], oB[j]);
                oB[j] = fmaf(wB[r*3+2], rowB[j+2], oB[j]);
            }
        }
        const unsigned Bb = su + OFF_B + (buf << 14);
#pragma unroll
        for (int j = 0; j < 8; j++) {
            const float hA = __bfloat162float(__float2bfloat16(oA[j]));
            const float hB = __bfloat162float(__float2bfloat16(oB[j]));
            const unsigned uh = pack_bf2(oB[j], oA[j]);        // lower = chA (k=2cp), upper = chB
            const unsigned ul = pack_bf2(oB[j] - hB, oA[j] - hA);
            const int p = (pg << 3) + j;
            const unsigned off = (unsigned)((p << 7) + (cp << 2));
            asm volatile("st.shared.b32 [%0], %1;" :: "r"(Bb + swz(off)), "r"(uh) : "memory");
            asm volatile("st.shared.b32 [%0], %1;" :: "r"(Bb + swz(off + 64)), "r"(ul) : "memory");
        }
    };

    // ---- mma block: chunk cm from B[bufm], A frags from registers ----
    auto mma_block = [&](int cm, int bufm, const uint4* a4) {
        const unsigned Bb = su + OFF_B + (bufm << 14);
#pragma unroll
        for (int ks = 0; ks < 4; ks++) {
            const int kb = ks << 5;
            unsigned bfr[4][4];
#pragma unroll
            for (int nb2 = 0; nb2 < 4; nb2++)
                ldm_x4(Bb + swz((unsigned)(((nw << 6) + (nb2 << 4) + bRow) << 7) + kb + bChunk), bfr[nb2]);
#pragma unroll
            for (int ma = 0; ma < 2; ma++)
#pragma unroll
                for (int nb = 0; nb < 8; nb++)
                    mma16816(acc[ma][nb], reinterpret_cast<const unsigned*>(&a4[ma * 4 + ks]),
                             bfr[nb >> 1][(nb & 1) << 1], bfr[nb >> 1][((nb & 1) << 1) + 1]);
        }
    };
    auto load_afrag = [&](int cm, uint4* a4) {
        const uint4* src = reinterpret_cast<const uint4*>(g_wpAf[MODE]) +
                           (((cm * 4 + mw) * 2) * 4) * 32 + lid;
#pragma unroll
        for (int ma = 0; ma < 2; ma++)
#pragma unroll
            for (int ks = 0; ks < 4; ks++)
                a4[ma * 4 + ks] = src[(ma * 4 + ks) * 32];
    };

    // ---- prologue: WD + chunk 0 halo ----
    {
        const char* srcw = reinterpret_cast<const char*>(g_wd[MODE]);
#pragma unroll
        for (int t = 0; t < 4; t++) {
            const int i = tid + (t << 8);
            if (i < 1008) cpa16(su + OFF_WD + i * 16, srcw + i * 16);
        }
        stage_in(0, 0);
        cp_commit();
    }

    // ---- body 0: dw(0) only ----
    cp_wait0();
    __syncthreads();
    stage_in(1, 1);
    cp_commit();
    dw_block(0, 0);

    // ---- main loop: dw(ci) || mma(ci-1) ----
    for (int ci = 1; ci < NCH; ci++) {
        const int buf = ci & 1;
        cp_wait0();            // halo(ci) complete (committed last body)
        __syncthreads();       // visibility + buffer protection
        if (ci + 1 < NCH) stage_in(ci + 1, buf ^ 1);
        cp_commit();
        uint4 a4[8];
        load_afrag(ci - 1, a4);
        dw_block(ci, buf);
        mma_block(ci - 1, buf ^ 1, a4);
    }

    // ---- tail: mma(13) ----
    __syncthreads();
    {
        uint4 a4[8];
        load_afrag(NCH - 1, a4);
        mma_block(NCH - 1, (NCH - 1) & 1, a4);
    }

    // ---- epilogue: acc regs -> smem stage -> coalesced global stores ----
    __syncthreads();
    float* s_ep = smf;          // 128 x 132 floats (overlaps B/WD/IN, all dead)
#pragma unroll
    for (int ma = 0; ma < 2; ma++)
#pragma unroll
        for (int nb = 0; nb < 8; nb++) {
            const int o0 = (mw << 5) + (ma << 4) + (lid >> 2);
            const int p0 = (nw << 6) + (nb << 3) + ((lid & 3) << 1);
            *reinterpret_cast<float2*>(&s_ep[o0 * EP_STRIDE + p0]) =
                make_float2(acc[ma][nb][0], acc[ma][nb][1]);
            *reinterpret_cast<float2*>(&s_ep[(o0 + 8) * EP_STRIDE + p0]) =
                make_float2(acc[ma][nb][2], acc[ma][nb][3]);
        }
    __syncthreads();

    const float ws = g_wpscale[MODE];
#pragma unroll
    for (int it = 0; it < 16; it++) {
        const int prr = it >> 2;
        const int o   = (tid >> 3) + ((it & 3) << 5);
        const int pcq = (tid & 7) << 2;
        const float bpv = __ldg(bp + o);
        const float4 d4 = *reinterpret_cast<const float4*>(&s_ep[o * EP_STRIDE + prr * 32 + pcq]);
        float4 v;
        v.x = fmaf(d4.x, ws, bpv); v.y = fmaf(d4.y, ws, bpv);
        v.z = fmaf(d4.z, ws, bpv); v.w = fmaf(d4.w, ws, bpv);
        const int gidx = (((b << 7) + o) << 13) + ((y0 + prr) << 7) + x0 + pcq;
        if (MODE == 0) {
            float4 r4 = make_float4(sigmoidf_(v.x), sigmoidf_(v.y), sigmoidf_(v.z), sigmoidf_(v.w));
            *reinterpret_cast<float4*>(&g_z[gidx]) = r4;
        } else if (MODE == 1) {
            const float4 h4 = *reinterpret_cast<const float4*>(&h[gidx]);
            float4 r4 = make_float4(h4.x * sigmoidf_(v.x), h4.y * sigmoidf_(v.y),
                                    h4.z * sigmoidf_(v.z), h4.w * sigmoidf_(v.w));
            *reinterpret_cast<float4*>(&g_rh[gidx]) = r4;
        } else {
            const float4 h4 = *reinterpret_cast<const float4*>(&h[gidx]);
            const float4 z4 = *reinterpret_cast<const float4*>(&g_z[gidx]);
            float4 r4;
            r4.x = fmaf(z4.x, tanhf(v.x) - h4.x, h4.x);
            r4.y = fmaf(z4.y, tanhf(v.y) - h4.y, h4.y);
            r4.z = fmaf(z4.z, tanhf(v.z) - h4.z, h4.z);
            r4.w = fmaf(z4.w, tanhf(v.w) - h4.w, h4.w);
            *reinterpret_cast<float4*>(&dout[gidx]) = r4;
        }
    }
}

// ---- launch ----
extern "C" void kernel_launch(void* const* d_in, const int* in_sizes, int n_in,
                              void* d_out, int out_size) {
    const float* h   = (const float*)d_in[0];
    const float* x   = (const float*)d_in[1];
    const float* wdz = (const float*)d_in[2];
    const float* bdz = (const float*)d_in[3];
    const float* wpz = (const float*)d_in[4];
    const float* bpz = (const float*)d_in[5];
    const float* wdr = (const float*)d_in[6];
    const float* bdr = (const float*)d_in[7];
    const float* wpr = (const float*)d_in[8];
    const float* bpr = (const float*)d_in[9];
    const float* wdq = (const float*)d_in[10];
    const float* bdq = (const float*)d_in[11];
    const float* wpq = (const float*)d_in[12];
    const float* bpq = (const float*)d_in[13];
    float* out = (float*)d_out;

    cudaFuncSetAttribute(gate_kernel<0>, cudaFuncAttributeMaxDynamicSharedMemorySize, SMEM_BYTES);
    cudaFuncSetAttribute(gate_kernel<1>, cudaFuncAttributeMaxDynamicSharedMemorySize, SMEM_BYTES);
    cudaFuncSetAttribute(gate_kernel<2>, cudaFuncAttributeMaxDynamicSharedMemorySize, SMEM_BYTES);

    quant_prep_kernel<<<6, 256>>>(wdz, wpz, wdr, wpr, wdq, wpq);

    dim3 grid(IMW / 32, IMH / 4, BATCH);   // (4, 16, 8) = 512 blocks
    gate_kernel<0><<<grid, 256, SMEM_BYTES>>>(h, x, bdz, bpz, nullptr);
    gate_kernel<1><<<grid, 256, SMEM_BYTES>>>(h, x, bdr, bpr, nullptr);
    gate_kernel<2><<<grid, 256, SMEM_BYTES>>>(h, x, bdq, bpq, out);
}